// round 13
// baseline (speedup 1.0000x reference)
#include <cuda_runtime.h>
#include <cstdint>

// x: [64, 3, 512, 512] float32
// keep_mask: [64, 32, 32] -> widened to 32-bit words (nonzero == keep)
// out = x * upsample16(keep_mask)
//
// R13 (final form): 4 warp-strided float4 slots per thread, 512-thread
// blocks (block tile = 2048 consecutive float4s = 32KB; slot stride =
// 512 float4s = 8KB).
//  - every LDG/STG: 32 lanes on consecutive float4s -> 4-line footprint
//  - 4 independent mask chains + 4 independently-predicated data loads
//    (MLP axis saturated here: 2->4 slots gained, 4->8 flat)
//  - masked-patch read elision (~32MB DRAM saved; at byte roofline:
//    332MB @ ~5.95TB/s effective)

static constexpr int B = 64;
static constexpr int C = 3;
static constexpr int H = 512;
static constexpr int W = 512;
static constexpr long long N  = (long long)B * C * H * W;  // 50,331,648 floats
static constexpr long long N4 = N / 4;                     // 12,582,912 float4s

static constexpr int THREADS = 512;
static constexpr int SLOTS   = 4;
// each block covers SLOTS*THREADS consecutive float4s
static constexpr long long BLOCKS = N4 / (SLOTS * THREADS); // 6144, exact

__device__ __forceinline__ bool mask_at(const uint32_t* __restrict__ keep,
                                        long long i /*float4 idx*/)
{
    long long base = i << 2;               // float index
    int w  = (int)(base & (W - 1));        // W = 512
    int h  = (int)((base >> 9) & (H - 1)); // H = 512
    int b  = (int)(base >> 18) / C;        // C = 3
    return __ldg(keep + b * 1024 + ((h >> 4) << 5) + (w >> 4)) != 0u;
}

__global__ void __launch_bounds__(THREADS) patchmask_kernel(
    const float4* __restrict__ x4,
    const uint32_t* __restrict__ keep,
    float4* __restrict__ out4)
{
    long long i0 = (long long)blockIdx.x * (SLOTS * THREADS) + threadIdx.x;

    bool m[SLOTS];
#pragma unroll
    for (int k = 0; k < SLOTS; k++)
        m[k] = mask_at(keep, i0 + (long long)k * THREADS);

    const float4 z = make_float4(0.f, 0.f, 0.f, 0.f);
    float4 v[SLOTS];
#pragma unroll
    for (int k = 0; k < SLOTS; k++)
        v[k] = m[k] ? __ldcs(x4 + i0 + (long long)k * THREADS) : z;

#pragma unroll
    for (int k = 0; k < SLOTS; k++)
        __stcs(out4 + i0 + (long long)k * THREADS, v[k]);
}

extern "C" void kernel_launch(void* const* d_in, const int* in_sizes, int n_in,
                              void* d_out, int out_size)
{
    const float4*   x4   = (const float4*)d_in[0];
    const uint32_t* keep = (const uint32_t*)d_in[1];
    float4*         out4 = (float4*)d_out;

    patchmask_kernel<<<(unsigned)BLOCKS, THREADS>>>(x4, keep, out4);
}

// round 14
// speedup vs baseline: 1.0043x; 1.0043x over previous
#include <cuda_runtime.h>
#include <cstdint>

// x: [64, 3, 512, 512] float32
// keep_mask: [64, 32, 32] -> widened to 32-bit words (nonzero == keep)
// out = x * upsample16(keep_mask)
//
// R14 (final): 4 warp-strided float4 slots/thread, 512-thread blocks,
// pure 32-bit index math (N4 = 12.58M < 2^31).
//  - every LDG/STG: 32 lanes on consecutive float4s (4-line footprint)
//  - 4 independent mask chains + 4 independently-predicated data loads
//  - masked-patch read elision (~32MB saved); at byte roofline
//    (332MB @ ~6.0TB/s effective -> ~54us kernel)

static constexpr int C = 3;
static constexpr int W = 512;
static constexpr int H = 512;
static constexpr unsigned N4 = 64u * 3u * 512u * 512u / 4u;  // 12,582,912

static constexpr int THREADS = 512;
static constexpr int SLOTS   = 4;
static constexpr unsigned BLOCKS = N4 / (SLOTS * THREADS);   // 6144, exact

__device__ __forceinline__ bool mask_at(const uint32_t* __restrict__ keep,
                                        unsigned i /*float4 idx*/)
{
    unsigned base = i << 2;                 // float index (fits 32-bit)
    unsigned w  = base & (W - 1);           // W = 512
    unsigned h  = (base >> 9) & (H - 1);    // H = 512
    unsigned b  = (base >> 18) / C;         // C = 3
    return __ldg(keep + (b << 10) + ((h >> 4) << 5) + (w >> 4)) != 0u;
}

__global__ void __launch_bounds__(THREADS) patchmask_kernel(
    const float4* __restrict__ x4,
    const uint32_t* __restrict__ keep,
    float4* __restrict__ out4)
{
    unsigned i0 = blockIdx.x * (SLOTS * THREADS) + threadIdx.x;

    bool m[SLOTS];
#pragma unroll
    for (int k = 0; k < SLOTS; k++)
        m[k] = mask_at(keep, i0 + k * THREADS);

    const float4 z = make_float4(0.f, 0.f, 0.f, 0.f);
    float4 v[SLOTS];
#pragma unroll
    for (int k = 0; k < SLOTS; k++)
        v[k] = m[k] ? __ldcs(x4 + i0 + k * THREADS) : z;

#pragma unroll
    for (int k = 0; k < SLOTS; k++)
        __stcs(out4 + i0 + k * THREADS, v[k]);
}

extern "C" void kernel_launch(void* const* d_in, const int* in_sizes, int n_in,
                              void* d_out, int out_size)
{
    const float4*   x4   = (const float4*)d_in[0];
    const uint32_t* keep = (const uint32_t*)d_in[1];
    float4*         out4 = (float4*)d_out;

    patchmask_kernel<<<BLOCKS, THREADS>>>(x4, keep, out4);
}

// round 16
// speedup vs baseline: 1.0097x; 1.0054x over previous
#include <cuda_runtime.h>
#include <cstdint>

// x: [64, 3, 512, 512] float32
// keep_mask: [64, 32, 32] -> widened to 32-bit words (nonzero == keep)
// out = x * upsample16(keep_mask)
//
// Final (== R14 champion): 4 warp-strided float4 slots/thread, 512-thread
// blocks, pure 32-bit index math (N4 = 12.58M < 2^31).
//  - every LDG/STG: 32 lanes on consecutive float4s (4-line footprint)
//  - 4 independent mask chains + 4 independently-predicated data loads
//  - masked-patch read elision (~32MB saved); at byte roofline
//    (332MB @ ~6.1TB/s effective -> ~53us kernel, DRAM ~76%)
//  - division by 3 left to the compiler (emits exact IMAD.HI magic-mul)

static constexpr int C = 3;
static constexpr int W = 512;
static constexpr int H = 512;
static constexpr unsigned N4 = 64u * 3u * 512u * 512u / 4u;  // 12,582,912

static constexpr int THREADS = 512;
static constexpr int SLOTS   = 4;
static constexpr unsigned BLOCKS = N4 / (SLOTS * THREADS);   // 6144, exact

__device__ __forceinline__ bool mask_at(const uint32_t* __restrict__ keep,
                                        unsigned i /*float4 idx*/)
{
    unsigned base = i << 2;                 // float index (fits 32-bit)
    unsigned w  = base & (W - 1);           // W = 512
    unsigned h  = (base >> 9) & (H - 1);    // H = 512
    unsigned b  = (base >> 18) / C;         // C = 3 (compiler magic-mul)
    return __ldg(keep + (b << 10) + ((h >> 4) << 5) + (w >> 4)) != 0u;
}

__global__ void __launch_bounds__(THREADS) patchmask_kernel(
    const float4* __restrict__ x4,
    const uint32_t* __restrict__ keep,
    float4* __restrict__ out4)
{
    unsigned i0 = blockIdx.x * (SLOTS * THREADS) + threadIdx.x;

    bool m[SLOTS];
#pragma unroll
    for (int k = 0; k < SLOTS; k++)
        m[k] = mask_at(keep, i0 + k * THREADS);

    const float4 z = make_float4(0.f, 0.f, 0.f, 0.f);
    float4 v[SLOTS];
#pragma unroll
    for (int k = 0; k < SLOTS; k++)
        v[k] = m[k] ? __ldcs(x4 + i0 + k * THREADS) : z;

#pragma unroll
    for (int k = 0; k < SLOTS; k++)
        __stcs(out4 + i0 + k * THREADS, v[k]);
}

extern "C" void kernel_launch(void* const* d_in, const int* in_sizes, int n_in,
                              void* d_out, int out_size)
{
    const float4*   x4   = (const float4*)d_in[0];
    const uint32_t* keep = (const uint32_t*)d_in[1];
    float4*         out4 = (float4*)d_out;

    patchmask_kernel<<<BLOCKS, THREADS>>>(x4, keep, out4);
}